// round 1
// baseline (speedup 1.0000x reference)
#include <cuda_runtime.h>
#include <math.h>

// Problem constants (fixed by the reference)
#define BB   4
#define SS   4096
#define EE   512
#define HH   8
#define DD   64
#define NT   (BB*SS)        // 16384 tokens
#define QW   1536           // 3*E

// ---------------- scratch (static device globals; no allocation) -------------
__device__ float g_qkv[(size_t)NT * QW];   // sig(q), sig(k), raw v  (96 MB)
__device__ float g_vals[(size_t)NT * EE];  // fused attention output (32 MB)
__device__ float g_sums[4 * 32 * 64];      // [sumQ, sumK, sqd, skd] x (bh=32) x (d=64)
__device__ float g_part[16 * 32 * 128];    // stage1 partials: [chunk][bh][qk*64+d]
__device__ float g_io[(size_t)NT * HH * 2];  // i at [tok*8+h], o at +NT*8
__device__ float g_hat[(size_t)NT * HH * 2]; // ihat, ohat (same layout)
__device__ float g_sm[64];                  // smax[0:32], ssum[32:64] per bh

// ---------------- SGEMM: C[m,n] = sum_k A[m,k]*B[n,k] + bias[n] --------------
// 128x128 tile, BK=16, 256 threads, 8x8 per thread. Optional sigmoid on
// columns with (n % 192) < 128 (the q/k slots of the fused QKV projection).
__global__ __launch_bounds__(256) void sgemm_nt(
    const float* __restrict__ A, const float* __restrict__ B,
    const float* __restrict__ bias, float* __restrict__ C,
    int M, int N, int K, int sigmode)
{
    const int BK = 16;
    __shared__ float As[BK][128];
    __shared__ float Bs[BK][128];

    const int bx = blockIdx.x;   // N tile
    const int by = blockIdx.y;   // M tile
    const int t  = threadIdx.x;
    const int tx = t & 15;
    const int ty = t >> 4;

    float acc[8][8];
#pragma unroll
    for (int i = 0; i < 8; i++)
#pragma unroll
        for (int j = 0; j < 8; j++) acc[i][j] = 0.f;

    const float* Ab = A + (size_t)by * 128 * K;
    const float* Bb = B + (size_t)bx * 128 * K;

    for (int k0 = 0; k0 < K; k0 += BK) {
#pragma unroll
        for (int r = 0; r < 2; r++) {
            int v   = t + r * 256;      // 0..511
            int row = v >> 2;
            int kk  = (v & 3) * 4;
            float4 a = *(const float4*)(Ab + (size_t)row * K + k0 + kk);
            As[kk + 0][row] = a.x; As[kk + 1][row] = a.y;
            As[kk + 2][row] = a.z; As[kk + 3][row] = a.w;
            float4 b = *(const float4*)(Bb + (size_t)row * K + k0 + kk);
            Bs[kk + 0][row] = b.x; Bs[kk + 1][row] = b.y;
            Bs[kk + 2][row] = b.z; Bs[kk + 3][row] = b.w;
        }
        __syncthreads();

#pragma unroll
        for (int kk = 0; kk < BK; kk++) {
            float ra[8], rb[8];
            *(float4*)(ra + 0) = *(const float4*)(&As[kk][ty * 8 + 0]);
            *(float4*)(ra + 4) = *(const float4*)(&As[kk][ty * 8 + 4]);
            *(float4*)(rb + 0) = *(const float4*)(&Bs[kk][tx * 8 + 0]);
            *(float4*)(rb + 4) = *(const float4*)(&Bs[kk][tx * 8 + 4]);
#pragma unroll
            for (int i = 0; i < 8; i++)
#pragma unroll
                for (int j = 0; j < 8; j++) acc[i][j] = fmaf(ra[i], rb[j], acc[i][j]);
        }
        __syncthreads();
    }

    // epilogue: bias + optional sigmoid on q/k columns, vectorized stores
    const int n0 = bx * 128 + tx * 8;
#pragma unroll
    for (int i = 0; i < 8; i++) {
        int m = by * 128 + ty * 8 + i;
        float* crow = C + (size_t)m * N + n0;
#pragma unroll
        for (int jj = 0; jj < 2; jj++) {
            float tmp[4];
#pragma unroll
            for (int q = 0; q < 4; q++) {
                int j = jj * 4 + q;
                int n = n0 + j;
                float val = acc[i][j] + bias[n];
                if (sigmode && ((n % 192) < 128)) val = 1.f / (1.f + __expf(-val));
                tmp[q] = val;
            }
            *(float4*)(crow + jj * 4) = make_float4(tmp[0], tmp[1], tmp[2], tmp[3]);
        }
    }
}

// ---------------- seq reductions: deterministic 2-stage ----------------------
// phase 0: sumQ[b,h,d] = sum_s q ; sumK = sum_s k
// phase 1: sqd = sum_s q / i[b,s,h] ; skd = sum_s k / o[b,s,h]
__global__ __launch_bounds__(128) void reduce_stage1(int phase)
{
    int chunk = blockIdx.x;            // 16 chunks of 256 seq positions
    int bh    = blockIdx.y;            // 32
    int b = bh >> 3, h = bh & 7;
    int tid = threadIdx.x;
    int isk = tid >> 6;                // 0: q, 1: k
    int d   = tid & 63;
    int s0  = chunk * (SS / 16);

    const float* base = g_qkv + ((size_t)(b * SS + s0)) * QW + h * 192 + isk * 64 + d;
    float acc = 0.f;
    if (phase == 0) {
        for (int s = 0; s < SS / 16; s++) acc += base[(size_t)s * QW];
    } else {
        const float* io = g_io + (isk ? (size_t)NT * 8 : 0) + ((size_t)(b * SS + s0)) * 8 + h;
        for (int s = 0; s < SS / 16; s++) acc += base[(size_t)s * QW] / io[(size_t)s * 8];
    }
    g_part[(chunk * 32 + bh) * 128 + tid] = acc;
}

__global__ __launch_bounds__(256) void reduce_stage2(int phase)
{
    int idx = blockIdx.x * 256 + threadIdx.x;   // 0..4095 = bh*128 + tid
    float acc = 0.f;
#pragma unroll
    for (int c = 0; c < 16; c++) acc += g_part[c * 4096 + idx];
    int bh = idx >> 7, t = idx & 127;
    int isk = t >> 6, d = t & 63;
    // slot order in g_sums: 0=sumQ, 1=sumK, 2=sqd, 3=skd
    g_sums[(size_t)(phase * 2 + isk) * 2048 + bh * 64 + d] = acc;
}

// ---------------- per-token dots: warp per token ------------------------------
// phase 0: i = q . sumK ; o = k . sumQ     -> g_io
// phase 1: ihat = q . skd ; ohat = k . sqd -> g_hat
__global__ __launch_bounds__(256) void dots_kernel(int phase)
{
    int warp = threadIdx.x >> 5, lane = threadIdx.x & 31;
    int tok  = blockIdx.x * 8 + warp;
    int b    = tok >> 12;

    __shared__ float sQ[8][64], sK[8][64];   // vectors paired with q / k resp.
    const float* vq = g_sums + (size_t)(phase == 0 ? 1 : 3) * 2048 + b * 512;
    const float* vk = g_sums + (size_t)(phase == 0 ? 0 : 2) * 2048 + b * 512;
    for (int idx = threadIdx.x; idx < 512; idx += 256) {
        sQ[idx >> 6][idx & 63] = vq[idx];
        sK[idx >> 6][idx & 63] = vk[idx];
    }
    __syncthreads();

    const float* tq = g_qkv + (size_t)tok * QW;
    float* outI = (phase == 0 ? g_io : g_hat) + (size_t)tok * 8;
    float* outO = outI + (size_t)NT * 8;

#pragma unroll
    for (int h = 0; h < 8; h++) {
        const float* qh = tq + h * 192;
        float vi = qh[lane] * sQ[h][lane] + qh[lane + 32] * sQ[h][lane + 32];
        float vo = qh[64 + lane] * sK[h][lane] + qh[64 + lane + 32] * sK[h][lane + 32];
#pragma unroll
        for (int off = 16; off; off >>= 1) {
            vi += __shfl_down_sync(0xFFFFFFFFu, vi, off);
            vo += __shfl_down_sync(0xFFFFFFFFu, vo, off);
        }
        if (lane == 0) { outI[h] = vi; outO[h] = vo; }
    }
}

// ---------------- softmax stats over seq per (b,h) ---------------------------
__global__ __launch_bounds__(256) void softmax_stats()
{
    int bh = blockIdx.x;
    int b = bh >> 3, h = bh & 7;
    __shared__ float red[256];
    const float* oh = g_hat + (size_t)NT * 8 + (size_t)b * SS * 8 + h;

    float m = -1e30f;
    for (int s = threadIdx.x; s < SS; s += 256) m = fmaxf(m, oh[(size_t)s * 8]);
    red[threadIdx.x] = m; __syncthreads();
    for (int o = 128; o; o >>= 1) {
        if (threadIdx.x < o) red[threadIdx.x] = fmaxf(red[threadIdx.x], red[threadIdx.x + o]);
        __syncthreads();
    }
    m = red[0]; __syncthreads();

    float sum = 0.f;
    for (int s = threadIdx.x; s < SS; s += 256) sum += expf(oh[(size_t)s * 8] - m);
    red[threadIdx.x] = sum; __syncthreads();
    for (int o = 128; o; o >>= 1) {
        if (threadIdx.x < o) red[threadIdx.x] += red[threadIdx.x + o];
        __syncthreads();
    }
    if (threadIdx.x == 0) { g_sm[bh] = m; g_sm[32 + bh] = red[0]; }
}

// ---------------- fused flow-attention core: 4 tokens per 256-thr block ------
// A[h,h'] = sum_d (q/i)[h,d] k[h',d];  r[h,e] = sig(ihat[h]) * sum_h' A * vw[h',e]
__global__ __launch_bounds__(256) void token_kernel()
{
    int lt = threadIdx.x >> 6;   // local token 0..3
    int e  = threadIdx.x & 63;
    int tok = blockIdx.x * 4 + lt;
    int b   = tok >> 12;

    __shared__ float qi[4][8][65], kk[4][8][65], vw[4][8][65];
    __shared__ float Am[4][8][9];
    __shared__ float s_invi[4][8], s_sig[4][8], s_sm[4][8];

    const float* tq = g_qkv + (size_t)tok * QW;
    if (e < 8) {
        int h = e;
        float iv = g_io[(size_t)tok * 8 + h];
        float ih = g_hat[(size_t)tok * 8 + h];
        float oh = g_hat[(size_t)NT * 8 + (size_t)tok * 8 + h];
        int bh = b * 8 + h;
        s_invi[lt][h] = 1.0f / iv;
        s_sig[lt][h]  = 1.0f / (1.0f + expf(-ih));
        s_sm[lt][h]   = expf(oh - g_sm[bh]) / g_sm[32 + bh];
    }
    __syncthreads();

#pragma unroll
    for (int h = 0; h < 8; h++) {
        qi[lt][h][e] = tq[h * 192 + e] * s_invi[lt][h];
        kk[lt][h][e] = tq[h * 192 + 64 + e];
        vw[lt][h][e] = tq[h * 192 + 128 + e] * s_sm[lt][h];
    }
    __syncthreads();

    {
        int h = e >> 3, h2 = e & 7;
        float a = 0.f;
#pragma unroll 8
        for (int d = 0; d < 64; d++) a = fmaf(qi[lt][h][d], kk[lt][h2][d], a);
        Am[lt][h][h2] = a;
    }
    __syncthreads();

    float* ov = g_vals + (size_t)tok * EE;
#pragma unroll
    for (int h = 0; h < 8; h++) {
        float acc = 0.f;
#pragma unroll
        for (int h2 = 0; h2 < 8; h2++) acc = fmaf(Am[lt][h][h2], vw[lt][h2][e], acc);
        ov[h * 64 + e] = acc * s_sig[lt][h];
    }
}

// ---------------- launch ------------------------------------------------------
extern "C" void kernel_launch(void* const* d_in, const int* in_sizes, int n_in,
                              void* d_out, int out_size)
{
    (void)in_sizes; (void)n_in; (void)out_size;
    const float* x     = (const float*)d_in[0];
    const float* W_qkv = (const float*)d_in[1];
    const float* b_qkv = (const float*)d_in[2];
    const float* W_out = (const float*)d_in[3];
    const float* b_out = (const float*)d_in[4];
    float* out = (float*)d_out;

    float *p_qkv = nullptr, *p_vals = nullptr;
    cudaGetSymbolAddress((void**)&p_qkv,  g_qkv);
    cudaGetSymbolAddress((void**)&p_vals, g_vals);

    // 1) QKV projection + sigmoid(q,k) epilogue   [16384 x 1536] = x @ W_qkv^T
    sgemm_nt<<<dim3(QW / 128, NT / 128), 256>>>(x, W_qkv, b_qkv, p_qkv,
                                                NT, QW, EE, 1);
    // 2) sumQ/sumK over seq
    reduce_stage1<<<dim3(16, 32), 128>>>(0);
    reduce_stage2<<<16, 256>>>(0);
    // 3) i, o per (token, head)
    dots_kernel<<<NT / 8, 256>>>(0);
    // 4) sqd = sum q/i, skd = sum k/o
    reduce_stage1<<<dim3(16, 32), 128>>>(1);
    reduce_stage2<<<16, 256>>>(1);
    // 5) ihat, ohat
    dots_kernel<<<NT / 8, 256>>>(1);
    // 6) softmax stats over seq per (b,h)
    softmax_stats<<<32, 256>>>();
    // 7) fused flow-attention core -> values
    token_kernel<<<NT / 4, 256>>>();
    // 8) output projection: out = values @ W_out^T + b_out
    sgemm_nt<<<dim3(EE / 128, NT / 128), 256>>>(p_vals, W_out, b_out, out,
                                                NT, EE, EE, 0);
}

// round 2
// speedup vs baseline: 1.0036x; 1.0036x over previous
#include <cuda_runtime.h>
#include <math.h>

// Problem constants (fixed by the reference)
#define BB   4
#define SS   4096
#define EE   512
#define HH   8
#define DD   64
#define NT   (BB*SS)        // 16384 tokens
#define QW   1536           // 3*E

// ---------------- scratch (static device globals; no allocation) -------------
__device__ float g_qkv[(size_t)NT * QW];   // sig(q), sig(k), raw v  (96 MB)
__device__ float g_vals[(size_t)NT * EE];  // fused attention output (32 MB)
__device__ float g_sums[4 * 32 * 64];      // [sumQ, sumK, sqd, skd] x (bh=32) x (d=64)
__device__ float g_part[16 * 32 * 128];    // stage1 partials: [chunk][bh][qk*64+d]
__device__ float g_io[(size_t)NT * HH * 2];  // i at [tok*8+h], o at +NT*8
__device__ float g_hat[(size_t)NT * HH * 2]; // ihat, ohat (same layout)
__device__ float g_sm[64];                  // smax[0:32], ssum[32:64] per bh

// ---------------- SGEMM: C[m,n] = sum_k A[m,k]*B[n,k] + bias[n] --------------
// 128x128 tile, BK=16, 256 threads, 8x8 per thread. Optional sigmoid on
// columns with (n % 192) < 128 (the q/k slots of the fused QKV projection).
__global__ __launch_bounds__(256) void sgemm_nt(
    const float* __restrict__ A, const float* __restrict__ B,
    const float* __restrict__ bias, float* __restrict__ C,
    int M, int N, int K, int sigmode)
{
    const int BK = 16;
    __shared__ float As[BK][128];
    __shared__ float Bs[BK][128];

    const int bx = blockIdx.x;   // N tile
    const int by = blockIdx.y;   // M tile
    const int t  = threadIdx.x;
    const int tx = t & 15;
    const int ty = t >> 4;

    float acc[8][8];
#pragma unroll
    for (int i = 0; i < 8; i++)
#pragma unroll
        for (int j = 0; j < 8; j++) acc[i][j] = 0.f;

    const float* Ab = A + (size_t)by * 128 * K;
    const float* Bb = B + (size_t)bx * 128 * K;

    for (int k0 = 0; k0 < K; k0 += BK) {
#pragma unroll
        for (int r = 0; r < 2; r++) {
            int v   = t + r * 256;      // 0..511
            int row = v >> 2;
            int kk  = (v & 3) * 4;
            float4 a = *(const float4*)(Ab + (size_t)row * K + k0 + kk);
            As[kk + 0][row] = a.x; As[kk + 1][row] = a.y;
            As[kk + 2][row] = a.z; As[kk + 3][row] = a.w;
            float4 b = *(const float4*)(Bb + (size_t)row * K + k0 + kk);
            Bs[kk + 0][row] = b.x; Bs[kk + 1][row] = b.y;
            Bs[kk + 2][row] = b.z; Bs[kk + 3][row] = b.w;
        }
        __syncthreads();

#pragma unroll
        for (int kk = 0; kk < BK; kk++) {
            float ra[8], rb[8];
            *(float4*)(ra + 0) = *(const float4*)(&As[kk][ty * 8 + 0]);
            *(float4*)(ra + 4) = *(const float4*)(&As[kk][ty * 8 + 4]);
            *(float4*)(rb + 0) = *(const float4*)(&Bs[kk][tx * 8 + 0]);
            *(float4*)(rb + 4) = *(const float4*)(&Bs[kk][tx * 8 + 4]);
#pragma unroll
            for (int i = 0; i < 8; i++)
#pragma unroll
                for (int j = 0; j < 8; j++) acc[i][j] = fmaf(ra[i], rb[j], acc[i][j]);
        }
        __syncthreads();
    }

    // epilogue: bias + optional sigmoid on q/k columns, vectorized stores
    const int n0 = bx * 128 + tx * 8;
#pragma unroll
    for (int i = 0; i < 8; i++) {
        int m = by * 128 + ty * 8 + i;
        float* crow = C + (size_t)m * N + n0;
#pragma unroll
        for (int jj = 0; jj < 2; jj++) {
            float tmp[4];
#pragma unroll
            for (int q = 0; q < 4; q++) {
                int j = jj * 4 + q;
                int n = n0 + j;
                float val = acc[i][j] + bias[n];
                if (sigmode && ((n % 192) < 128)) val = 1.f / (1.f + __expf(-val));
                tmp[q] = val;
            }
            *(float4*)(crow + jj * 4) = make_float4(tmp[0], tmp[1], tmp[2], tmp[3]);
        }
    }
}

// ---------------- seq reductions: deterministic 2-stage ----------------------
// phase 0: sumQ[b,h,d] = sum_s q ; sumK = sum_s k
// phase 1: sqd = sum_s q / i[b,s,h] ; skd = sum_s k / o[b,s,h]
__global__ __launch_bounds__(128) void reduce_stage1(int phase)
{
    int chunk = blockIdx.x;            // 16 chunks of 256 seq positions
    int bh    = blockIdx.y;            // 32
    int b = bh >> 3, h = bh & 7;
    int tid = threadIdx.x;
    int isk = tid >> 6;                // 0: q, 1: k
    int d   = tid & 63;
    int s0  = chunk * (SS / 16);

    const float* base = g_qkv + ((size_t)(b * SS + s0)) * QW + h * 192 + isk * 64 + d;
    float acc = 0.f;
    if (phase == 0) {
        for (int s = 0; s < SS / 16; s++) acc += base[(size_t)s * QW];
    } else {
        const float* io = g_io + (isk ? (size_t)NT * 8 : 0) + ((size_t)(b * SS + s0)) * 8 + h;
        for (int s = 0; s < SS / 16; s++) acc += base[(size_t)s * QW] / io[(size_t)s * 8];
    }
    g_part[(chunk * 32 + bh) * 128 + tid] = acc;
}

__global__ __launch_bounds__(256) void reduce_stage2(int phase)
{
    int idx = blockIdx.x * 256 + threadIdx.x;   // 0..4095 = bh*128 + tid
    float acc = 0.f;
#pragma unroll
    for (int c = 0; c < 16; c++) acc += g_part[c * 4096 + idx];
    int bh = idx >> 7, t = idx & 127;
    int isk = t >> 6, d = t & 63;
    // slot order in g_sums: 0=sumQ, 1=sumK, 2=sqd, 3=skd
    g_sums[(size_t)(phase * 2 + isk) * 2048 + bh * 64 + d] = acc;
}

// ---------------- per-token dots: warp per token ------------------------------
// phase 0: i = q . sumK ; o = k . sumQ     -> g_io
// phase 1: ihat = q . skd ; ohat = k . sqd -> g_hat
__global__ __launch_bounds__(256) void dots_kernel(int phase)
{
    int warp = threadIdx.x >> 5, lane = threadIdx.x & 31;
    int tok  = blockIdx.x * 8 + warp;
    int b    = tok >> 12;

    __shared__ float sQ[8][64], sK[8][64];   // vectors paired with q / k resp.
    const float* vq = g_sums + (size_t)(phase == 0 ? 1 : 3) * 2048 + b * 512;
    const float* vk = g_sums + (size_t)(phase == 0 ? 0 : 2) * 2048 + b * 512;
    for (int idx = threadIdx.x; idx < 512; idx += 256) {
        sQ[idx >> 6][idx & 63] = vq[idx];
        sK[idx >> 6][idx & 63] = vk[idx];
    }
    __syncthreads();

    const float* tq = g_qkv + (size_t)tok * QW;
    float* outI = (phase == 0 ? g_io : g_hat) + (size_t)tok * 8;
    float* outO = outI + (size_t)NT * 8;

#pragma unroll
    for (int h = 0; h < 8; h++) {
        const float* qh = tq + h * 192;
        float vi = qh[lane] * sQ[h][lane] + qh[lane + 32] * sQ[h][lane + 32];
        float vo = qh[64 + lane] * sK[h][lane] + qh[64 + lane + 32] * sK[h][lane + 32];
#pragma unroll
        for (int off = 16; off; off >>= 1) {
            vi += __shfl_down_sync(0xFFFFFFFFu, vi, off);
            vo += __shfl_down_sync(0xFFFFFFFFu, vo, off);
        }
        if (lane == 0) { outI[h] = vi; outO[h] = vo; }
    }
}

// ---------------- softmax stats over seq per (b,h) ---------------------------
__global__ __launch_bounds__(256) void softmax_stats()
{
    int bh = blockIdx.x;
    int b = bh >> 3, h = bh & 7;
    __shared__ float red[256];
    const float* oh = g_hat + (size_t)NT * 8 + (size_t)b * SS * 8 + h;

    float m = -1e30f;
    for (int s = threadIdx.x; s < SS; s += 256) m = fmaxf(m, oh[(size_t)s * 8]);
    red[threadIdx.x] = m; __syncthreads();
    for (int o = 128; o; o >>= 1) {
        if (threadIdx.x < o) red[threadIdx.x] = fmaxf(red[threadIdx.x], red[threadIdx.x + o]);
        __syncthreads();
    }
    m = red[0]; __syncthreads();

    float sum = 0.f;
    for (int s = threadIdx.x; s < SS; s += 256) sum += expf(oh[(size_t)s * 8] - m);
    red[threadIdx.x] = sum; __syncthreads();
    for (int o = 128; o; o >>= 1) {
        if (threadIdx.x < o) red[threadIdx.x] += red[threadIdx.x + o];
        __syncthreads();
    }
    if (threadIdx.x == 0) { g_sm[bh] = m; g_sm[32 + bh] = red[0]; }
}

// ---------------- fused flow-attention core: 4 tokens per 256-thr block ------
// A[h,h'] = sum_d (q/i)[h,d] k[h',d];  r[h,e] = sig(ihat[h]) * sum_h' A * vw[h',e]
__global__ __launch_bounds__(256) void token_kernel()
{
    int lt = threadIdx.x >> 6;   // local token 0..3
    int e  = threadIdx.x & 63;
    int tok = blockIdx.x * 4 + lt;
    int b   = tok >> 12;

    __shared__ float qi[4][8][65], kk[4][8][65], vw[4][8][65];
    __shared__ float Am[4][8][9];
    __shared__ float s_invi[4][8], s_sig[4][8], s_sm[4][8];

    const float* tq = g_qkv + (size_t)tok * QW;
    if (e < 8) {
        int h = e;
        float iv = g_io[(size_t)tok * 8 + h];
        float ih = g_hat[(size_t)tok * 8 + h];
        float oh = g_hat[(size_t)NT * 8 + (size_t)tok * 8 + h];
        int bh = b * 8 + h;
        s_invi[lt][h] = 1.0f / iv;
        s_sig[lt][h]  = 1.0f / (1.0f + expf(-ih));
        s_sm[lt][h]   = expf(oh - g_sm[bh]) / g_sm[32 + bh];
    }
    __syncthreads();

#pragma unroll
    for (int h = 0; h < 8; h++) {
        qi[lt][h][e] = tq[h * 192 + e] * s_invi[lt][h];
        kk[lt][h][e] = tq[h * 192 + 64 + e];
        vw[lt][h][e] = tq[h * 192 + 128 + e] * s_sm[lt][h];
    }
    __syncthreads();

    {
        int h = e >> 3, h2 = e & 7;
        float a = 0.f;
#pragma unroll 8
        for (int d = 0; d < 64; d++) a = fmaf(qi[lt][h][d], kk[lt][h2][d], a);
        Am[lt][h][h2] = a;
    }
    __syncthreads();

    float* ov = g_vals + (size_t)tok * EE;
#pragma unroll
    for (int h = 0; h < 8; h++) {
        float acc = 0.f;
#pragma unroll
        for (int h2 = 0; h2 < 8; h2++) acc = fmaf(Am[lt][h][h2], vw[lt][h2][e], acc);
        ov[h * 64 + e] = acc * s_sig[lt][h];
    }
}

// ---------------- launch ------------------------------------------------------
extern "C" void kernel_launch(void* const* d_in, const int* in_sizes, int n_in,
                              void* d_out, int out_size)
{
    (void)in_sizes; (void)n_in; (void)out_size;
    const float* x     = (const float*)d_in[0];
    const float* W_qkv = (const float*)d_in[1];
    const float* b_qkv = (const float*)d_in[2];
    const float* W_out = (const float*)d_in[3];
    const float* b_out = (const float*)d_in[4];
    float* out = (float*)d_out;

    float *p_qkv = nullptr, *p_vals = nullptr;
    cudaGetSymbolAddress((void**)&p_qkv,  g_qkv);
    cudaGetSymbolAddress((void**)&p_vals, g_vals);

    // 1) QKV projection + sigmoid(q,k) epilogue   [16384 x 1536] = x @ W_qkv^T
    sgemm_nt<<<dim3(QW / 128, NT / 128), 256>>>(x, W_qkv, b_qkv, p_qkv,
                                                NT, QW, EE, 1);
    // 2) sumQ/sumK over seq
    reduce_stage1<<<dim3(16, 32), 128>>>(0);
    reduce_stage2<<<16, 256>>>(0);
    // 3) i, o per (token, head)
    dots_kernel<<<NT / 8, 256>>>(0);
    // 4) sqd = sum q/i, skd = sum k/o
    reduce_stage1<<<dim3(16, 32), 128>>>(1);
    reduce_stage2<<<16, 256>>>(1);
    // 5) ihat, ohat
    dots_kernel<<<NT / 8, 256>>>(1);
    // 6) softmax stats over seq per (b,h)
    softmax_stats<<<32, 256>>>();
    // 7) fused flow-attention core -> values
    token_kernel<<<NT / 4, 256>>>();
    // 8) output projection: out = values @ W_out^T + b_out
    sgemm_nt<<<dim3(EE / 128, NT / 128), 256>>>(p_vals, W_out, b_out, out,
                                                NT, EE, EE, 0);
}

// round 4
// speedup vs baseline: 1.9489x; 1.9419x over previous
#include <cuda_runtime.h>
#include <cuda_bf16.h>
#include <math.h>
#include <stdint.h>

// Problem constants (fixed by the reference)
#define BB   4
#define SS   4096
#define EE   512
#define HH   8
#define DD   64
#define NT   (BB*SS)        // 16384 tokens
#define QW   1536           // 3*E

// ---------------- scratch (static device globals; no allocation) -------------
__device__ float g_qkv[(size_t)NT * QW];   // sig(q), sig(k), raw v  (96 MB)
__device__ float g_vals[(size_t)NT * EE];  // fused attention output (32 MB)
__device__ float g_sums[4 * 32 * 64];      // [sumQ, sumK, sqd, skd] x (bh=32) x (d=64)
__device__ float g_part[16 * 32 * 128];    // stage1 partials
__device__ float g_io[(size_t)NT * HH * 2];  // i at [tok*8+h], o at +NT*8
__device__ float g_hat[(size_t)NT * HH * 2]; // ihat, ohat
__device__ float g_sm[64];                   // smax[0:32], ssum[32:64]

// ===================== portable tensor-core helpers (sm_80+ PTX) =============
__device__ __forceinline__ uint32_t smem_u32(const void* p) {
    uint32_t a;
    asm("{ .reg .u64 t; cvta.to.shared.u64 t, %1; cvt.u32.u64 %0, t; }"
        : "=r"(a) : "l"(p));
    return a;
}

#define LDSM_X4(r0, r1, r2, r3, addr) \
    asm volatile("ldmatrix.sync.aligned.m8n8.x4.shared.b16 {%0,%1,%2,%3}, [%4];" \
        : "=r"(r0), "=r"(r1), "=r"(r2), "=r"(r3) : "r"(addr))

#define MMA_BF16(d, a, b) \
    asm volatile("mma.sync.aligned.m16n8k16.row.col.f32.bf16.bf16.f32 " \
        "{%0,%1,%2,%3},{%4,%5,%6,%7},{%8,%9},{%0,%1,%2,%3};" \
        : "+f"((d)[0]), "+f"((d)[1]), "+f"((d)[2]), "+f"((d)[3]) \
        : "r"((a)[0]), "r"((a)[1]), "r"((a)[2]), "r"((a)[3]), \
          "r"((b)[0]), "r"((b)[1]))

#define STS_V2(addr, x, y) \
    asm volatile("st.shared.v2.u32 [%0], {%1,%2};" :: "r"(addr), "r"(x), "r"(y))

// SMEM tile geometry: rows of 32 bf16 padded to 40 elements (80 bytes).
// 80B pitch => the 8 row-addresses of every ldmatrix phase land on distinct
// 16B banks (r*80 mod 128 = {0,80,32,112,64,16,96,48}) — conflict-free, no xor.
#define PITCH_B   80u
#define PLANE_B   10240u               // 128 rows * 80B
#define STAGE_B   40960u               // Ahi, Alo, Bhi, Blo planes
#define SMEM_GEMM (2 * STAGE_B)        // 81920 bytes, double buffered

__device__ __forceinline__ void cvt_sts(uint32_t hi_addr, uint32_t lo_addr, float4 v)
{
    __nv_bfloat16 h0 = __float2bfloat16(v.x);
    __nv_bfloat16 h1 = __float2bfloat16(v.y);
    __nv_bfloat16 h2 = __float2bfloat16(v.z);
    __nv_bfloat16 h3 = __float2bfloat16(v.w);
    __nv_bfloat162 hp0 = __nv_bfloat162(h0, h1);
    __nv_bfloat162 hp1 = __nv_bfloat162(h2, h3);
    __nv_bfloat162 lp0 = __floats2bfloat162_rn(v.x - __bfloat162float(h0),
                                               v.y - __bfloat162float(h1));
    __nv_bfloat162 lp1 = __floats2bfloat162_rn(v.z - __bfloat162float(h2),
                                               v.w - __bfloat162float(h3));
    STS_V2(hi_addr, *(uint32_t*)&hp0, *(uint32_t*)&hp1);
    STS_V2(lo_addr, *(uint32_t*)&lp0, *(uint32_t*)&lp1);
}

__device__ __forceinline__ void ldg8(const float* __restrict__ Ab,
                                     const float* __restrict__ Bb,
                                     int K, int k0, int tid,
                                     float4* ra, float4* rb)
{
#pragma unroll
    for (int it = 0; it < 4; it++) {
        int idx = it * 256 + tid;
        int row = idx >> 3;
        int c   = idx & 7;
        ra[it] = *(const float4*)(Ab + (size_t)row * K + k0 + c * 4);
        rb[it] = *(const float4*)(Bb + (size_t)row * K + k0 + c * 4);
    }
}

__device__ __forceinline__ void sts8(uint32_t sbase, int tid,
                                     const float4* ra, const float4* rb)
{
#pragma unroll
    for (int it = 0; it < 4; it++) {
        int idx = it * 256 + tid;
        int row = idx >> 3;
        int c   = idx & 7;
        uint32_t byte = (uint32_t)row * PITCH_B + (uint32_t)c * 8u;
        cvt_sts(sbase + byte,               sbase + PLANE_B     + byte, ra[it]);
        cvt_sts(sbase + 2u * PLANE_B + byte, sbase + 3u * PLANE_B + byte, rb[it]);
    }
}

// ======== HMMA split-bf16 GEMM: C[m,n] = sum_k A[m,k]B[n,k] + bias[n] ========
// 128x128 tile, BK=32, 256 threads = 8 warps (2 M x 4 N), warp tile 64x32.
// 3 bf16 products (AhiBhi + AhiBlo + AloBhi) emulate fp32.
__global__ __launch_bounds__(256, 1) void hmma_gemm(
    const float* __restrict__ A, const float* __restrict__ B,
    const float* __restrict__ bias, float* __restrict__ C,
    int N, int K, int sigmode)
{
    extern __shared__ char dynsmem[];
    const uint32_t sbase = smem_u32(dynsmem);

    const int tid   = threadIdx.x;
    const int warp  = tid >> 5;
    const int lane  = tid & 31;
    const int warpM = warp & 1;        // 0..1 -> 64-row slab
    const int warpN = warp >> 1;       // 0..3 -> 32-col slab

    const float* Ab = A + (size_t)blockIdx.y * 128 * K;
    const float* Bb = B + (size_t)blockIdx.x * 128 * K;

    float acc[16][4];
#pragma unroll
    for (int i = 0; i < 16; i++)
#pragma unroll
        for (int j = 0; j < 4; j++) acc[i][j] = 0.f;

    const int NC = K >> 5;             // 32-wide K chunks

    // precomputed ldmatrix lane offsets (bytes within a plane)
    const uint32_t a_lane = (uint32_t)(warpM * 64 + (lane & 15)) * PITCH_B
                          + (uint32_t)((lane >> 4) * 16);
    const uint32_t b_lane = (uint32_t)(warpN * 32 + (lane & 7) + ((lane >> 4) & 1) * 8) * PITCH_B
                          + (uint32_t)(((lane >> 3) & 1) * 16);

    float4 ra[4], rb[4];
    ldg8(Ab, Bb, K, 0, tid, ra, rb);
    sts8(sbase, tid, ra, rb);
    __syncthreads();

    for (int c = 0; c < NC; c++) {
        const uint32_t cur = sbase + (uint32_t)(c & 1) * STAGE_B;
        if (c + 1 < NC) ldg8(Ab, Bb, K, (c + 1) * 32, tid, ra, rb);

#pragma unroll
        for (int ks = 0; ks < 2; ks++) {
            const uint32_t koff = (uint32_t)ks * 32u;
            uint32_t ah[4][4], al[4][4], bh[4][2], bl[4][2];
#pragma unroll
            for (int mi = 0; mi < 4; mi++) {
                uint32_t addr = cur + a_lane + (uint32_t)(mi * 16) * PITCH_B + koff;
                LDSM_X4(ah[mi][0], ah[mi][1], ah[mi][2], ah[mi][3], addr);
                LDSM_X4(al[mi][0], al[mi][1], al[mi][2], al[mi][3], addr + PLANE_B);
            }
#pragma unroll
            for (int p = 0; p < 2; p++) {
                uint32_t addr = cur + 2u * PLANE_B + b_lane
                              + (uint32_t)(p * 16) * PITCH_B + koff;
                LDSM_X4(bh[2*p][0], bh[2*p][1], bh[2*p+1][0], bh[2*p+1][1], addr);
                LDSM_X4(bl[2*p][0], bl[2*p][1], bl[2*p+1][0], bl[2*p+1][1],
                        addr + PLANE_B);
            }
#pragma unroll
            for (int mi = 0; mi < 4; mi++)
#pragma unroll
                for (int ni = 0; ni < 4; ni++) {
                    MMA_BF16(acc[mi * 4 + ni], ah[mi], bh[ni]);
                    MMA_BF16(acc[mi * 4 + ni], ah[mi], bl[ni]);
                    MMA_BF16(acc[mi * 4 + ni], al[mi], bh[ni]);
                }
        }

        if (c + 1 < NC) {
            sts8(sbase + (uint32_t)((c + 1) & 1) * STAGE_B, tid, ra, rb);
            __syncthreads();
        }
    }

    // ---- epilogue: bias + optional sigmoid, direct stores ----
#pragma unroll
    for (int mi = 0; mi < 4; mi++) {
        const int r0 = blockIdx.y * 128 + warpM * 64 + mi * 16 + (lane >> 2);
#pragma unroll
        for (int ni = 0; ni < 4; ni++) {
            const int col = blockIdx.x * 128 + warpN * 32 + ni * 8 + (lane & 3) * 2;
            const float b0 = __ldg(bias + col);
            const float b1 = __ldg(bias + col + 1);
            const bool s0 = sigmode && ((col % 192) < 128);
            const bool s1 = sigmode && (((col + 1) % 192) < 128);
            float v0 = acc[mi * 4 + ni][0] + b0;
            float v1 = acc[mi * 4 + ni][1] + b1;
            float v2 = acc[mi * 4 + ni][2] + b0;
            float v3 = acc[mi * 4 + ni][3] + b1;
            if (s0) { v0 = 1.f / (1.f + __expf(-v0)); v2 = 1.f / (1.f + __expf(-v2)); }
            if (s1) { v1 = 1.f / (1.f + __expf(-v1)); v3 = 1.f / (1.f + __expf(-v3)); }
            *(float2*)(C + (size_t)r0 * N + col)       = make_float2(v0, v1);
            *(float2*)(C + (size_t)(r0 + 8) * N + col) = make_float2(v2, v3);
        }
    }
}

// ---------------- seq reductions: deterministic 2-stage ----------------------
__global__ __launch_bounds__(128) void reduce_stage1(int phase)
{
    int chunk = blockIdx.x;
    int bh    = blockIdx.y;
    int b = bh >> 3, h = bh & 7;
    int tid = threadIdx.x;
    int isk = tid >> 6;
    int d   = tid & 63;
    int s0  = chunk * (SS / 16);

    const float* base = g_qkv + ((size_t)(b * SS + s0)) * QW + h * 192 + isk * 64 + d;
    float acc = 0.f;
    if (phase == 0) {
        for (int s = 0; s < SS / 16; s++) acc += base[(size_t)s * QW];
    } else {
        const float* io = g_io + (isk ? (size_t)NT * 8 : 0) + ((size_t)(b * SS + s0)) * 8 + h;
        for (int s = 0; s < SS / 16; s++) acc += base[(size_t)s * QW] / io[(size_t)s * 8];
    }
    g_part[(chunk * 32 + bh) * 128 + tid] = acc;
}

__global__ __launch_bounds__(256) void reduce_stage2(int phase)
{
    int idx = blockIdx.x * 256 + threadIdx.x;
    float acc = 0.f;
#pragma unroll
    for (int c = 0; c < 16; c++) acc += g_part[c * 4096 + idx];
    int bh = idx >> 7, t = idx & 127;
    int isk = t >> 6, d = t & 63;
    g_sums[(size_t)(phase * 2 + isk) * 2048 + bh * 64 + d] = acc;
}

// ---------------- per-token dots: warp per token ------------------------------
__global__ __launch_bounds__(256) void dots_kernel(int phase)
{
    int warp = threadIdx.x >> 5, lane = threadIdx.x & 31;
    int tok  = blockIdx.x * 8 + warp;
    int b    = tok >> 12;

    __shared__ float sQ[8][64], sK[8][64];
    const float* vq = g_sums + (size_t)(phase == 0 ? 1 : 3) * 2048 + b * 512;
    const float* vk = g_sums + (size_t)(phase == 0 ? 0 : 2) * 2048 + b * 512;
    for (int idx = threadIdx.x; idx < 512; idx += 256) {
        sQ[idx >> 6][idx & 63] = vq[idx];
        sK[idx >> 6][idx & 63] = vk[idx];
    }
    __syncthreads();

    const float* tq = g_qkv + (size_t)tok * QW;
    float* outI = (phase == 0 ? g_io : g_hat) + (size_t)tok * 8;
    float* outO = outI + (size_t)NT * 8;

#pragma unroll
    for (int h = 0; h < 8; h++) {
        const float* qh = tq + h * 192;
        float vi = qh[lane] * sQ[h][lane] + qh[lane + 32] * sQ[h][lane + 32];
        float vo = qh[64 + lane] * sK[h][lane] + qh[64 + lane + 32] * sK[h][lane + 32];
#pragma unroll
        for (int off = 16; off; off >>= 1) {
            vi += __shfl_down_sync(0xFFFFFFFFu, vi, off);
            vo += __shfl_down_sync(0xFFFFFFFFu, vo, off);
        }
        if (lane == 0) { outI[h] = vi; outO[h] = vo; }
    }
}

// ---------------- softmax stats over seq per (b,h) ---------------------------
__global__ __launch_bounds__(256) void softmax_stats()
{
    int bh = blockIdx.x;
    int b = bh >> 3, h = bh & 7;
    __shared__ float red[256];
    const float* oh = g_hat + (size_t)NT * 8 + (size_t)b * SS * 8 + h;

    float m = -1e30f;
    for (int s = threadIdx.x; s < SS; s += 256) m = fmaxf(m, oh[(size_t)s * 8]);
    red[threadIdx.x] = m; __syncthreads();
    for (int o = 128; o; o >>= 1) {
        if (threadIdx.x < o) red[threadIdx.x] = fmaxf(red[threadIdx.x], red[threadIdx.x + o]);
        __syncthreads();
    }
    m = red[0]; __syncthreads();

    float sum = 0.f;
    for (int s = threadIdx.x; s < SS; s += 256) sum += expf(oh[(size_t)s * 8] - m);
    red[threadIdx.x] = sum; __syncthreads();
    for (int o = 128; o; o >>= 1) {
        if (threadIdx.x < o) red[threadIdx.x] += red[threadIdx.x + o];
        __syncthreads();
    }
    if (threadIdx.x == 0) { g_sm[bh] = m; g_sm[32 + bh] = red[0]; }
}

// ---------------- fused flow-attention core -----------------------------------
__global__ __launch_bounds__(256) void token_kernel()
{
    int lt = threadIdx.x >> 6;
    int e  = threadIdx.x & 63;
    int tok = blockIdx.x * 4 + lt;
    int b   = tok >> 12;

    __shared__ float qi[4][8][65], kk[4][8][65], vw[4][8][65];
    __shared__ float Am[4][8][9];
    __shared__ float s_invi[4][8], s_sig[4][8], s_sm[4][8];

    const float* tq = g_qkv + (size_t)tok * QW;
    if (e < 8) {
        int h = e;
        float iv = g_io[(size_t)tok * 8 + h];
        float ih = g_hat[(size_t)tok * 8 + h];
        float oh = g_hat[(size_t)NT * 8 + (size_t)tok * 8 + h];
        int bh = b * 8 + h;
        s_invi[lt][h] = 1.0f / iv;
        s_sig[lt][h]  = 1.0f / (1.0f + expf(-ih));
        s_sm[lt][h]   = expf(oh - g_sm[bh]) / g_sm[32 + bh];
    }
    __syncthreads();

#pragma unroll
    for (int h = 0; h < 8; h++) {
        qi[lt][h][e] = tq[h * 192 + e] * s_invi[lt][h];
        kk[lt][h][e] = tq[h * 192 + 64 + e];
        vw[lt][h][e] = tq[h * 192 + 128 + e] * s_sm[lt][h];
    }
    __syncthreads();

    {
        int h = e >> 3, h2 = e & 7;
        float a = 0.f;
#pragma unroll 8
        for (int d = 0; d < 64; d++) a = fmaf(qi[lt][h][d], kk[lt][h2][d], a);
        Am[lt][h][h2] = a;
    }
    __syncthreads();

    float* ov = g_vals + (size_t)tok * EE;
#pragma unroll
    for (int h = 0; h < 8; h++) {
        float acc = 0.f;
#pragma unroll
        for (int h2 = 0; h2 < 8; h2++) acc = fmaf(Am[lt][h][h2], vw[lt][h2][e], acc);
        ov[h * 64 + e] = acc * s_sig[lt][h];
    }
}

// ---------------- launch ------------------------------------------------------
extern "C" void kernel_launch(void* const* d_in, const int* in_sizes, int n_in,
                              void* d_out, int out_size)
{
    (void)in_sizes; (void)n_in; (void)out_size;
    const float* x     = (const float*)d_in[0];
    const float* W_qkv = (const float*)d_in[1];
    const float* b_qkv = (const float*)d_in[2];
    const float* W_out = (const float*)d_in[3];
    const float* b_out = (const float*)d_in[4];
    float* out = (float*)d_out;

    float *p_qkv = nullptr, *p_vals = nullptr;
    cudaGetSymbolAddress((void**)&p_qkv,  g_qkv);
    cudaGetSymbolAddress((void**)&p_vals, g_vals);

    cudaFuncSetAttribute(hmma_gemm, cudaFuncAttributeMaxDynamicSharedMemorySize,
                         SMEM_GEMM);

    // 1) QKV projection (HMMA split-bf16) + sigmoid(q,k) epilogue
    hmma_gemm<<<dim3(QW / 128, NT / 128), 256, SMEM_GEMM>>>(
        x, W_qkv, b_qkv, p_qkv, QW, EE, 1);
    // 2) sumQ/sumK over seq
    reduce_stage1<<<dim3(16, 32), 128>>>(0);
    reduce_stage2<<<16, 256>>>(0);
    // 3) i, o per (token, head)
    dots_kernel<<<NT / 8, 256>>>(0);
    // 4) sqd = sum q/i, skd = sum k/o
    reduce_stage1<<<dim3(16, 32), 128>>>(1);
    reduce_stage2<<<16, 256>>>(1);
    // 5) ihat, ohat
    dots_kernel<<<NT / 8, 256>>>(1);
    // 6) softmax stats
    softmax_stats<<<32, 256>>>();
    // 7) fused flow-attention core -> values
    token_kernel<<<NT / 4, 256>>>();
    // 8) output projection (HMMA split-bf16)
    hmma_gemm<<<dim3(EE / 128, NT / 128), 256, SMEM_GEMM>>>(
        p_vals, W_out, b_out, out, EE, EE, 0);
}

// round 6
// speedup vs baseline: 2.1414x; 1.0988x over previous
#include <cuda_runtime.h>
#include <cuda_fp16.h>
#include <math.h>
#include <stdint.h>

// Problem constants (fixed by the reference)
#define BB   4
#define SS   4096
#define EE   512
#define HH   8
#define DD   64
#define NT   (BB*SS)        // 16384 tokens
#define QW   1536           // 3*E

#define VAL_SCALE     1048576.0f          // 2^20: lift values out of fp16 subnormals
#define VAL_INV_SCALE (1.0f / 1048576.0f)

// ---------------- scratch (static device globals; no allocation) -------------
__device__ float g_qkv[(size_t)NT * QW];   // sig(q), sig(k), raw v  (96 MB)
__device__ float g_sums[4 * 32 * 64];
__device__ float g_part[16 * 32 * 128];
__device__ float g_io[(size_t)NT * HH * 2];
__device__ float g_hat[(size_t)NT * HH * 2];
__device__ float g_sm[64];
// fp16 hi/lo GEMM operands
__device__ __half g_xhi[(size_t)NT * EE];
__device__ __half g_xlo[(size_t)NT * EE];
__device__ __half g_whi[(size_t)QW * EE];   // W_qkv hi
__device__ __half g_wohi[(size_t)EE * EE];  // W_out hi
__device__ __half g_vhi[(size_t)NT * EE];   // values*2^20 hi (GEMM2 A)
__device__ __half g_vlo[(size_t)NT * EE];   // values*2^20 lo

// ===================== portable PTX helpers (sm_80+) =========================
__device__ __forceinline__ uint32_t smem_u32(const void* p) {
    uint32_t a;
    asm("{ .reg .u64 t; cvta.to.shared.u64 t, %1; cvt.u32.u64 %0, t; }"
        : "=r"(a) : "l"(p));
    return a;
}
#define LDSM_X4(r0, r1, r2, r3, addr) \
    asm volatile("ldmatrix.sync.aligned.m8n8.x4.shared.b16 {%0,%1,%2,%3}, [%4];" \
        : "=r"(r0), "=r"(r1), "=r"(r2), "=r"(r3) : "r"(addr))
#define MMA_F16(d, a, b) \
    asm volatile("mma.sync.aligned.m16n8k16.row.col.f32.f16.f16.f32 " \
        "{%0,%1,%2,%3},{%4,%5,%6,%7},{%8,%9},{%0,%1,%2,%3};" \
        : "+f"((d)[0]), "+f"((d)[1]), "+f"((d)[2]), "+f"((d)[3]) \
        : "r"((a)[0]), "r"((a)[1]), "r"((a)[2]), "r"((a)[3]), \
          "r"((b)[0]), "r"((b)[1]))
#define CP_ASYNC16(dst, src) \
    asm volatile("cp.async.cg.shared.global [%0], [%1], 16;" \
        :: "r"(dst), "l"(src))
#define CP_COMMIT() asm volatile("cp.async.commit_group;" ::: "memory")
#define CP_WAIT(n)  asm volatile("cp.async.wait_group %0;" :: "n"(n) : "memory")

// SMEM geometry: rows of 32 fp16 (64B) padded to 80B (16B-aligned; the 8
// row-addresses of each ldmatrix phase land on distinct 16B banks).
#define PITCH_B   80u
#define PLANE_B   10240u               // 128 rows * 80B
#define STAGE_B   30720u               // Ahi, Alo, Bhi planes
#define NSTAGE    4
#define SMEM_GEMM (NSTAGE * STAGE_B)   // 122880 bytes

// ======== HMMA split-fp16 GEMM: C[m,n] = sum_k A[m,k]B[n,k] + bias[n] ========
// A supplied as fp16 hi+lo, B as fp16 hi. 2 products: Ahi*Bhi + Alo*Bhi.
// 128x128 tile, BK=32, 256 threads = 8 warps (2M x 4N), warp tile 64x32.
__device__ __forceinline__ void issue_stage(
    uint32_t sbase, int stage, int k0,
    const __half* __restrict__ ahi, const __half* __restrict__ alo,
    const __half* __restrict__ bhi, int K, int tid)
{
    const uint32_t sb = sbase + (uint32_t)stage * STAGE_B;
#pragma unroll
    for (int it = 0; it < 6; it++) {
        int idx   = it * 256 + tid;          // 0..1535
        int plane = idx >> 9;                // 0..2
        int rc    = idx & 511;
        int row   = rc >> 2;
        int c     = rc & 3;
        uint32_t dst = sb + (uint32_t)plane * PLANE_B
                     + (uint32_t)row * PITCH_B + (uint32_t)c * 16u;
        const __half* src = (plane == 0 ? ahi : (plane == 1 ? alo : bhi))
                          + (size_t)row * K + k0 + c * 8;
        CP_ASYNC16(dst, src);
    }
}

__global__ __launch_bounds__(256, 1) void hmma_gemm(
    const __half* __restrict__ Ahi, const __half* __restrict__ Alo,
    const __half* __restrict__ Bhi,
    const float* __restrict__ bias, float* __restrict__ C,
    int N, int K, int sigmode, float ascale)
{
    extern __shared__ char dynsmem[];
    const uint32_t sbase = smem_u32(dynsmem);

    const int tid   = threadIdx.x;
    const int warp  = tid >> 5;
    const int lane  = tid & 31;
    const int warpM = warp & 1;
    const int warpN = warp >> 1;

    const __half* ahi = Ahi + (size_t)blockIdx.y * 128 * K;
    const __half* alo = Alo + (size_t)blockIdx.y * 128 * K;
    const __half* bhi = Bhi + (size_t)blockIdx.x * 128 * K;

    float acc[16][4];
#pragma unroll
    for (int i = 0; i < 16; i++)
#pragma unroll
        for (int j = 0; j < 4; j++) acc[i][j] = 0.f;

    const int NC = K >> 5;   // chunks of 32

    const uint32_t a_lane = (uint32_t)(warpM * 64 + (lane & 15)) * PITCH_B
                          + (uint32_t)((lane >> 4) * 16);
    const uint32_t b_lane = (uint32_t)(warpN * 32 + (lane & 7) + ((lane >> 4) & 1) * 8) * PITCH_B
                          + (uint32_t)(((lane >> 3) & 1) * 16);

    // prologue: fill NSTAGE-1 stages
#pragma unroll
    for (int s = 0; s < NSTAGE - 1; s++) {
        issue_stage(sbase, s, s * 32, ahi, alo, bhi, K, tid);
        CP_COMMIT();
    }

    for (int c = 0; c < NC; c++) {
        if (c > 0) __syncthreads();          // all warps done with buffer to refill
        if (c + NSTAGE - 1 < NC)
            issue_stage(sbase, (c + NSTAGE - 1) % NSTAGE, (c + NSTAGE - 1) * 32,
                        ahi, alo, bhi, K, tid);
        CP_COMMIT();
        CP_WAIT(NSTAGE - 2);
        __syncthreads();

        const uint32_t cur = sbase + (uint32_t)(c % NSTAGE) * STAGE_B;
#pragma unroll
        for (int ks = 0; ks < 2; ks++) {
            const uint32_t koff = (uint32_t)ks * 32u;   // 16 fp16 = 32B
            uint32_t ah[4][4], al[4][4], bh[4][2];
#pragma unroll
            for (int mi = 0; mi < 4; mi++) {
                uint32_t addr = cur + a_lane + (uint32_t)(mi * 16) * PITCH_B + koff;
                LDSM_X4(ah[mi][0], ah[mi][1], ah[mi][2], ah[mi][3], addr);
                LDSM_X4(al[mi][0], al[mi][1], al[mi][2], al[mi][3], addr + PLANE_B);
            }
#pragma unroll
            for (int p = 0; p < 2; p++) {
                uint32_t addr = cur + 2u * PLANE_B + b_lane
                              + (uint32_t)(p * 16) * PITCH_B + koff;
                LDSM_X4(bh[2*p][0], bh[2*p][1], bh[2*p+1][0], bh[2*p+1][1], addr);
            }
#pragma unroll
            for (int mi = 0; mi < 4; mi++)
#pragma unroll
                for (int ni = 0; ni < 4; ni++) {
                    MMA_F16(acc[mi * 4 + ni], ah[mi], bh[ni]);
                    MMA_F16(acc[mi * 4 + ni], al[mi], bh[ni]);
                }
        }
    }

    // ---- epilogue: unscale + bias + optional sigmoid ----
#pragma unroll
    for (int mi = 0; mi < 4; mi++) {
        const int r0 = blockIdx.y * 128 + warpM * 64 + mi * 16 + (lane >> 2);
#pragma unroll
        for (int ni = 0; ni < 4; ni++) {
            const int col = blockIdx.x * 128 + warpN * 32 + ni * 8 + (lane & 3) * 2;
            const float b0 = __ldg(bias + col);
            const float b1 = __ldg(bias + col + 1);
            const bool s0 = sigmode && ((col % 192) < 128);
            const bool s1 = sigmode && (((col + 1) % 192) < 128);
            float v0 = acc[mi * 4 + ni][0] * ascale + b0;
            float v1 = acc[mi * 4 + ni][1] * ascale + b1;
            float v2 = acc[mi * 4 + ni][2] * ascale + b0;
            float v3 = acc[mi * 4 + ni][3] * ascale + b1;
            if (s0) { v0 = 1.f / (1.f + __expf(-v0)); v2 = 1.f / (1.f + __expf(-v2)); }
            if (s1) { v1 = 1.f / (1.f + __expf(-v1)); v3 = 1.f / (1.f + __expf(-v3)); }
            *(float2*)(C + (size_t)r0 * N + col)       = make_float2(v0, v1);
            *(float2*)(C + (size_t)(r0 + 8) * N + col) = make_float2(v2, v3);
        }
    }
}

// ---------------- fp32 -> fp16 hi/lo converters -------------------------------
__global__ __launch_bounds__(256) void cvt_split(
    const float4* __restrict__ src, __half2* __restrict__ hi,
    __half2* __restrict__ lo, int n4)
{
    int i = blockIdx.x * 256 + threadIdx.x;
    if (i >= n4) return;
    float4 v = src[i];
    __half h0 = __float2half(v.x), h1 = __float2half(v.y);
    __half h2 = __float2half(v.z), h3 = __float2half(v.w);
    hi[2 * i]     = __half2(h0, h1);
    hi[2 * i + 1] = __half2(h2, h3);
    lo[2 * i]     = __half2(__float2half(v.x - __half2float(h0)),
                            __float2half(v.y - __half2float(h1)));
    lo[2 * i + 1] = __half2(__float2half(v.z - __half2float(h2)),
                            __float2half(v.w - __half2float(h3)));
}

__global__ __launch_bounds__(256) void cvt_hi(
    const float4* __restrict__ src, __half2* __restrict__ hi, int n4)
{
    int i = blockIdx.x * 256 + threadIdx.x;
    if (i >= n4) return;
    float4 v = src[i];
    hi[2 * i]     = __half2(__float2half(v.x), __float2half(v.y));
    hi[2 * i + 1] = __half2(__float2half(v.z), __float2half(v.w));
}

// ---------------- seq reductions: deterministic 2-stage ----------------------
__global__ __launch_bounds__(128) void reduce_stage1(int phase)
{
    int chunk = blockIdx.x;
    int bh    = blockIdx.y;
    int b = bh >> 3, h = bh & 7;
    int tid = threadIdx.x;
    int isk = tid >> 6;
    int d   = tid & 63;
    int s0  = chunk * (SS / 16);

    const float* base = g_qkv + ((size_t)(b * SS + s0)) * QW + h * 192 + isk * 64 + d;
    float acc = 0.f;
    if (phase == 0) {
        for (int s = 0; s < SS / 16; s++) acc += base[(size_t)s * QW];
    } else {
        const float* io = g_io + (isk ? (size_t)NT * 8 : 0) + ((size_t)(b * SS + s0)) * 8 + h;
        for (int s = 0; s < SS / 16; s++) acc += base[(size_t)s * QW] / io[(size_t)s * 8];
    }
    g_part[(chunk * 32 + bh) * 128 + tid] = acc;
}

__global__ __launch_bounds__(256) void reduce_stage2(int phase)
{
    int idx = blockIdx.x * 256 + threadIdx.x;
    float acc = 0.f;
#pragma unroll
    for (int c = 0; c < 16; c++) acc += g_part[c * 4096 + idx];
    int bh = idx >> 7, t = idx & 127;
    int isk = t >> 6, d = t & 63;
    g_sums[(size_t)(phase * 2 + isk) * 2048 + bh * 64 + d] = acc;
}

// ---------------- per-token dots: warp per token ------------------------------
__global__ __launch_bounds__(256) void dots_kernel(int phase)
{
    int warp = threadIdx.x >> 5, lane = threadIdx.x & 31;
    int tok  = blockIdx.x * 8 + warp;
    int b    = tok >> 12;

    __shared__ float sQ[8][64], sK[8][64];
    const float* vq = g_sums + (size_t)(phase == 0 ? 1 : 3) * 2048 + b * 512;
    const float* vk = g_sums + (size_t)(phase == 0 ? 0 : 2) * 2048 + b * 512;
    for (int idx = threadIdx.x; idx < 512; idx += 256) {
        sQ[idx >> 6][idx & 63] = vq[idx];
        sK[idx >> 6][idx & 63] = vk[idx];
    }
    __syncthreads();

    const float* tq = g_qkv + (size_t)tok * QW;
    float* outI = (phase == 0 ? g_io : g_hat) + (size_t)tok * 8;
    float* outO = outI + (size_t)NT * 8;

#pragma unroll
    for (int h = 0; h < 8; h++) {
        const float* qh = tq + h * 192;
        float vi = qh[lane] * sQ[h][lane] + qh[lane + 32] * sQ[h][lane + 32];
        float vo = qh[64 + lane] * sK[h][lane] + qh[64 + lane + 32] * sK[h][lane + 32];
#pragma unroll
        for (int off = 16; off; off >>= 1) {
            vi += __shfl_down_sync(0xFFFFFFFFu, vi, off);
            vo += __shfl_down_sync(0xFFFFFFFFu, vo, off);
        }
        if (lane == 0) { outI[h] = vi; outO[h] = vo; }
    }
}

// ---------------- softmax stats over seq per (b,h) ---------------------------
__global__ __launch_bounds__(256) void softmax_stats()
{
    int bh = blockIdx.x;
    int b = bh >> 3, h = bh & 7;
    __shared__ float red[256];
    const float* oh = g_hat + (size_t)NT * 8 + (size_t)b * SS * 8 + h;

    float m = -1e30f;
    for (int s = threadIdx.x; s < SS; s += 256) m = fmaxf(m, oh[(size_t)s * 8]);
    red[threadIdx.x] = m; __syncthreads();
    for (int o = 128; o; o >>= 1) {
        if (threadIdx.x < o) red[threadIdx.x] = fmaxf(red[threadIdx.x], red[threadIdx.x + o]);
        __syncthreads();
    }
    m = red[0]; __syncthreads();

    float sum = 0.f;
    for (int s = threadIdx.x; s < SS; s += 256) sum += expf(oh[(size_t)s * 8] - m);
    red[threadIdx.x] = sum; __syncthreads();
    for (int o = 128; o; o >>= 1) {
        if (threadIdx.x < o) red[threadIdx.x] += red[threadIdx.x + o];
        __syncthreads();
    }
    if (threadIdx.x == 0) { g_sm[bh] = m; g_sm[32 + bh] = red[0]; }
}

// -------- fused flow-attention core (emits scaled fp16 hi/lo values) ---------
__global__ __launch_bounds__(256) void token_kernel()
{
    int lt = threadIdx.x >> 6;
    int e  = threadIdx.x & 63;
    int tok = blockIdx.x * 4 + lt;
    int b   = tok >> 12;

    __shared__ float qi[4][8][65], kk[4][8][65], vw[4][8][65];
    __shared__ float Am[4][8][9];
    __shared__ float s_invi[4][8], s_sig[4][8], s_sm[4][8];

    const float* tq = g_qkv + (size_t)tok * QW;
    if (e < 8) {
        int h = e;
        float iv = g_io[(size_t)tok * 8 + h];
        float ih = g_hat[(size_t)tok * 8 + h];
        float oh = g_hat[(size_t)NT * 8 + (size_t)tok * 8 + h];
        int bh = b * 8 + h;
        s_invi[lt][h] = 1.0f / iv;
        s_sig[lt][h]  = 1.0f / (1.0f + expf(-ih));
        s_sm[lt][h]   = expf(oh - g_sm[bh]) / g_sm[32 + bh];
    }
    __syncthreads();

#pragma unroll
    for (int h = 0; h < 8; h++) {
        qi[lt][h][e] = tq[h * 192 + e] * s_invi[lt][h];
        kk[lt][h][e] = tq[h * 192 + 64 + e];
        vw[lt][h][e] = tq[h * 192 + 128 + e] * s_sm[lt][h];
    }
    __syncthreads();

    {
        int h = e >> 3, h2 = e & 7;
        float a = 0.f;
#pragma unroll 8
        for (int d = 0; d < 64; d++) a = fmaf(qi[lt][h][d], kk[lt][h2][d], a);
        Am[lt][h][h2] = a;
    }
    __syncthreads();

    __half* ovh = g_vhi + (size_t)tok * EE;
    __half* ovl = g_vlo + (size_t)tok * EE;
#pragma unroll
    for (int h = 0; h < 8; h++) {
        float acc = 0.f;
#pragma unroll
        for (int h2 = 0; h2 < 8; h2++) acc = fmaf(Am[lt][h][h2], vw[lt][h2][e], acc);
        // scale by 2^20 so fp16 hi/lo stay in the normal range (values ~1e-7)
        float vs = acc * s_sig[lt][h] * VAL_SCALE;
        __half hv = __float2half(vs);
        ovh[h * 64 + e] = hv;
        ovl[h * 64 + e] = __float2half(vs - __half2float(hv));
    }
}

// ---------------- launch ------------------------------------------------------
extern "C" void kernel_launch(void* const* d_in, const int* in_sizes, int n_in,
                              void* d_out, int out_size)
{
    (void)in_sizes; (void)n_in; (void)out_size;
    const float* x     = (const float*)d_in[0];
    const float* W_qkv = (const float*)d_in[1];
    const float* b_qkv = (const float*)d_in[2];
    const float* W_out = (const float*)d_in[3];
    const float* b_out = (const float*)d_in[4];
    float* out = (float*)d_out;

    float* p_qkv = nullptr;
    cudaGetSymbolAddress((void**)&p_qkv, g_qkv);
    __half *p_xhi, *p_xlo, *p_whi, *p_wohi, *p_vhi, *p_vlo;
    cudaGetSymbolAddress((void**)&p_xhi,  g_xhi);
    cudaGetSymbolAddress((void**)&p_xlo,  g_xlo);
    cudaGetSymbolAddress((void**)&p_whi,  g_whi);
    cudaGetSymbolAddress((void**)&p_wohi, g_wohi);
    cudaGetSymbolAddress((void**)&p_vhi,  g_vhi);
    cudaGetSymbolAddress((void**)&p_vlo,  g_vlo);

    cudaFuncSetAttribute(hmma_gemm, cudaFuncAttributeMaxDynamicSharedMemorySize,
                         SMEM_GEMM);

    // 0) convert operands to fp16 hi/lo
    {
        int n4 = NT * EE / 4;
        cvt_split<<<(n4 + 255) / 256, 256>>>((const float4*)x,
                                             (__half2*)p_xhi, (__half2*)p_xlo, n4);
        int w4 = QW * EE / 4;
        cvt_hi<<<(w4 + 255) / 256, 256>>>((const float4*)W_qkv, (__half2*)p_whi, w4);
        int o4 = EE * EE / 4;
        cvt_hi<<<(o4 + 255) / 256, 256>>>((const float4*)W_out, (__half2*)p_wohi, o4);
    }
    // 1) QKV projection (HMMA split-fp16) + sigmoid(q,k) epilogue
    hmma_gemm<<<dim3(QW / 128, NT / 128), 256, SMEM_GEMM>>>(
        p_xhi, p_xlo, p_whi, b_qkv, p_qkv, QW, EE, 1, 1.0f);
    // 2) sumQ/sumK over seq
    reduce_stage1<<<dim3(16, 32), 128>>>(0);
    reduce_stage2<<<16, 256>>>(0);
    // 3) i, o per (token, head)
    dots_kernel<<<NT / 8, 256>>>(0);
    // 4) sqd = sum q/i, skd = sum k/o
    reduce_stage1<<<dim3(16, 32), 128>>>(1);
    reduce_stage2<<<16, 256>>>(1);
    // 5) ihat, ohat
    dots_kernel<<<NT / 8, 256>>>(1);
    // 6) softmax stats
    softmax_stats<<<32, 256>>>();
    // 7) fused flow-attention core -> scaled values (fp16 hi/lo)
    token_kernel<<<NT / 4, 256>>>();
    // 8) output projection (HMMA split-fp16), unscale in epilogue
    hmma_gemm<<<dim3(EE / 128, NT / 128), 256, SMEM_GEMM>>>(
        p_vhi, p_vlo, p_wohi, b_out, out, EE, EE, 0, VAL_INV_SCALE);
}

// round 7
// speedup vs baseline: 2.3459x; 1.0955x over previous
#include <cuda_runtime.h>
#include <cuda_fp16.h>
#include <math.h>
#include <stdint.h>

// Problem constants (fixed by the reference)
#define BB   4
#define SS   4096
#define EE   512
#define HH   8
#define DD   64
#define NT   (BB*SS)        // 16384 tokens
#define QW   1536           // 3*E

#define VAL_SCALE     1048576.0f          // 2^20: lift values out of fp16 subnormals
#define VAL_INV_SCALE (1.0f / 1048576.0f)

// ---------------- scratch (static device globals; no allocation) -------------
__device__ float g_qkv[(size_t)NT * QW];   // sig(q), sig(k), raw v  (96 MB)
__device__ float g_sums[4 * 32 * 64];
__device__ float g_part[16 * 32 * 128];
__device__ float g_io[(size_t)NT * HH * 2];
__device__ float g_hat[(size_t)NT * HH * 2];
__device__ float g_sm[64];
// fp16 hi/lo GEMM operands
__device__ __half g_xhi[(size_t)NT * EE];
__device__ __half g_xlo[(size_t)NT * EE];
__device__ __half g_whi[(size_t)QW * EE];   // W_qkv hi
__device__ __half g_wohi[(size_t)EE * EE];  // W_out hi
__device__ __half g_vhi[(size_t)NT * EE];   // values*2^20 hi (GEMM2 A)
__device__ __half g_vlo[(size_t)NT * EE];   // values*2^20 lo

// ===================== portable PTX helpers (sm_80+) =========================
__device__ __forceinline__ uint32_t smem_u32(const void* p) {
    uint32_t a;
    asm("{ .reg .u64 t; cvta.to.shared.u64 t, %1; cvt.u32.u64 %0, t; }"
        : "=r"(a) : "l"(p));
    return a;
}
#define LDSM_X4(r0, r1, r2, r3, addr) \
    asm volatile("ldmatrix.sync.aligned.m8n8.x4.shared.b16 {%0,%1,%2,%3}, [%4];" \
        : "=r"(r0), "=r"(r1), "=r"(r2), "=r"(r3) : "r"(addr))
#define MMA_F16(d, a, b) \
    asm volatile("mma.sync.aligned.m16n8k16.row.col.f32.f16.f16.f32 " \
        "{%0,%1,%2,%3},{%4,%5,%6,%7},{%8,%9},{%0,%1,%2,%3};" \
        : "+f"((d)[0]), "+f"((d)[1]), "+f"((d)[2]), "+f"((d)[3]) \
        : "r"((a)[0]), "r"((a)[1]), "r"((a)[2]), "r"((a)[3]), \
          "r"((b)[0]), "r"((b)[1]))
#define CP_ASYNC16(dst, src) \
    asm volatile("cp.async.cg.shared.global [%0], [%1], 16;" \
        :: "r"(dst), "l"(src))
#define CP_COMMIT() asm volatile("cp.async.commit_group;" ::: "memory")
#define CP_WAIT(n)  asm volatile("cp.async.wait_group %0;" :: "n"(n) : "memory")

// SMEM geometry: rows of 32 fp16 (64B) padded to 80B (16B-aligned; the 8
// row-addresses of each ldmatrix phase land on distinct 16B banks).
#define PITCH_B   80u
#define PLANE_A   20480u               // 256 rows * 80B   (A hi / A lo planes)
#define PLANE_BP  10240u               // 128 rows * 80B   (B hi plane)
#define STAGE_B   51200u               // Ahi + Alo + Bhi
#define NSTAGE    4
#define SMEM_GEMM (NSTAGE * STAGE_B)   // 204800 bytes

// ======== HMMA split-fp16 GEMM: C[m,n] = sum_k A[m,k]B[n,k] + bias[n] ========
// A supplied as fp16 hi+lo, B as fp16 hi. 2 products: Ahi*Bhi + Alo*Bhi.
// 256x128 tile, BK=32, 512 threads = 16 warps (4M x 4N), warp tile 64x32.
__device__ __forceinline__ void issue_stage(
    uint32_t sbase, int stage, int k0,
    const __half* __restrict__ ahi, const __half* __restrict__ alo,
    const __half* __restrict__ bhi, int K, int tid)
{
    const uint32_t sb = sbase + (uint32_t)stage * STAGE_B;
    // A hi: 256 rows x 4 x 16B  (its 0..1)
#pragma unroll
    for (int it = 0; it < 2; it++) {
        int idx = it * 512 + tid;
        int r = idx >> 2, c = idx & 3;
        CP_ASYNC16(sb + (uint32_t)r * PITCH_B + (uint32_t)c * 16u,
                   ahi + (size_t)r * K + k0 + c * 8);
    }
    // A lo
#pragma unroll
    for (int it = 0; it < 2; it++) {
        int idx = it * 512 + tid;
        int r = idx >> 2, c = idx & 3;
        CP_ASYNC16(sb + PLANE_A + (uint32_t)r * PITCH_B + (uint32_t)c * 16u,
                   alo + (size_t)r * K + k0 + c * 8);
    }
    // B hi: 128 rows x 4 x 16B
    {
        int r = tid >> 2, c = tid & 3;
        CP_ASYNC16(sb + 2u * PLANE_A + (uint32_t)r * PITCH_B + (uint32_t)c * 16u,
                   bhi + (size_t)r * K + k0 + c * 8);
    }
}

__global__ __launch_bounds__(512, 1) void hmma_gemm(
    const __half* __restrict__ Ahi, const __half* __restrict__ Alo,
    const __half* __restrict__ Bhi,
    const float* __restrict__ bias, float* __restrict__ C,
    int N, int K, int sigmode, float ascale)
{
    extern __shared__ char dynsmem[];
    const uint32_t sbase = smem_u32(dynsmem);

    const int tid   = threadIdx.x;
    const int warp  = tid >> 5;
    const int lane  = tid & 31;
    const int warpM = warp & 3;        // 4 x 64-row slabs
    const int warpN = warp >> 2;       // 4 x 32-col slabs

    const __half* ahi = Ahi + (size_t)blockIdx.y * 256 * K;
    const __half* alo = Alo + (size_t)blockIdx.y * 256 * K;
    const __half* bhi = Bhi + (size_t)blockIdx.x * 128 * K;

    float acc[16][4];
#pragma unroll
    for (int i = 0; i < 16; i++)
#pragma unroll
        for (int j = 0; j < 4; j++) acc[i][j] = 0.f;

    const int NC = K >> 5;   // chunks of 32

    const uint32_t a_lane = (uint32_t)(warpM * 64 + (lane & 15)) * PITCH_B
                          + (uint32_t)((lane >> 4) * 16);
    const uint32_t b_lane = 2u * PLANE_A
                          + (uint32_t)(warpN * 32 + (lane & 7) + ((lane >> 4) & 1) * 8) * PITCH_B
                          + (uint32_t)(((lane >> 3) & 1) * 16);

    // prologue: fill NSTAGE-1 stages
#pragma unroll
    for (int s = 0; s < NSTAGE - 1; s++) {
        issue_stage(sbase, s, s * 32, ahi, alo, bhi, K, tid);
        CP_COMMIT();
    }

    for (int c = 0; c < NC; c++) {
        CP_WAIT(NSTAGE - 2);
        __syncthreads();   // stage c resident; slot (c-1)%N free for refill
        if (c + NSTAGE - 1 < NC)
            issue_stage(sbase, (c + NSTAGE - 1) % NSTAGE, (c + NSTAGE - 1) * 32,
                        ahi, alo, bhi, K, tid);
        CP_COMMIT();

        const uint32_t cur = sbase + (uint32_t)(c % NSTAGE) * STAGE_B;
#pragma unroll
        for (int ks = 0; ks < 2; ks++) {
            const uint32_t koff = (uint32_t)ks * 32u;   // 16 fp16 = 32B
            uint32_t bh[4][2];
#pragma unroll
            for (int p = 0; p < 2; p++) {
                uint32_t addr = cur + b_lane + (uint32_t)(p * 16) * PITCH_B + koff;
                LDSM_X4(bh[2*p][0], bh[2*p][1], bh[2*p+1][0], bh[2*p+1][1], addr);
            }
#pragma unroll
            for (int mi = 0; mi < 4; mi++) {
                uint32_t ah[4], al[4];
                uint32_t addr = cur + a_lane + (uint32_t)(mi * 16) * PITCH_B + koff;
                LDSM_X4(ah[0], ah[1], ah[2], ah[3], addr);
                LDSM_X4(al[0], al[1], al[2], al[3], addr + PLANE_A);
#pragma unroll
                for (int ni = 0; ni < 4; ni++) {
                    MMA_F16(acc[mi * 4 + ni], ah, bh[ni]);
                    MMA_F16(acc[mi * 4 + ni], al, bh[ni]);
                }
            }
        }
    }

    // ---- epilogue: unscale + bias + optional sigmoid ----
#pragma unroll
    for (int mi = 0; mi < 4; mi++) {
        const int r0 = blockIdx.y * 256 + warpM * 64 + mi * 16 + (lane >> 2);
#pragma unroll
        for (int ni = 0; ni < 4; ni++) {
            const int col = blockIdx.x * 128 + warpN * 32 + ni * 8 + (lane & 3) * 2;
            const float b0 = __ldg(bias + col);
            const float b1 = __ldg(bias + col + 1);
            const bool s0 = sigmode && ((col % 192) < 128);
            const bool s1 = sigmode && (((col + 1) % 192) < 128);
            float v0 = acc[mi * 4 + ni][0] * ascale + b0;
            float v1 = acc[mi * 4 + ni][1] * ascale + b1;
            float v2 = acc[mi * 4 + ni][2] * ascale + b0;
            float v3 = acc[mi * 4 + ni][3] * ascale + b1;
            if (s0) { v0 = 1.f / (1.f + __expf(-v0)); v2 = 1.f / (1.f + __expf(-v2)); }
            if (s1) { v1 = 1.f / (1.f + __expf(-v1)); v3 = 1.f / (1.f + __expf(-v3)); }
            *(float2*)(C + (size_t)r0 * N + col)       = make_float2(v0, v1);
            *(float2*)(C + (size_t)(r0 + 8) * N + col) = make_float2(v2, v3);
        }
    }
}

// ---------------- fp32 -> fp16 hi/lo converters -------------------------------
__global__ __launch_bounds__(256) void cvt_split(
    const float4* __restrict__ src, __half2* __restrict__ hi,
    __half2* __restrict__ lo, int n4)
{
    int i = blockIdx.x * 256 + threadIdx.x;
    if (i >= n4) return;
    float4 v = src[i];
    __half h0 = __float2half(v.x), h1 = __float2half(v.y);
    __half h2 = __float2half(v.z), h3 = __float2half(v.w);
    hi[2 * i]     = __half2(h0, h1);
    hi[2 * i + 1] = __half2(h2, h3);
    lo[2 * i]     = __half2(__float2half(v.x - __half2float(h0)),
                            __float2half(v.y - __half2float(h1)));
    lo[2 * i + 1] = __half2(__float2half(v.z - __half2float(h2)),
                            __float2half(v.w - __half2float(h3)));
}

__global__ __launch_bounds__(256) void cvt_hi(
    const float4* __restrict__ src, __half2* __restrict__ hi, int n4)
{
    int i = blockIdx.x * 256 + threadIdx.x;
    if (i >= n4) return;
    float4 v = src[i];
    hi[2 * i]     = __half2(__float2half(v.x), __float2half(v.y));
    hi[2 * i + 1] = __half2(__float2half(v.z), __float2half(v.w));
}

// ---------------- seq reductions: deterministic 2-stage ----------------------
__global__ __launch_bounds__(128) void reduce_stage1(int phase)
{
    int chunk = blockIdx.x;
    int bh    = blockIdx.y;
    int b = bh >> 3, h = bh & 7;
    int tid = threadIdx.x;
    int isk = tid >> 6;
    int d   = tid & 63;
    int s0  = chunk * (SS / 16);

    const float* base = g_qkv + ((size_t)(b * SS + s0)) * QW + h * 192 + isk * 64 + d;
    float acc = 0.f;
    if (phase == 0) {
        for (int s = 0; s < SS / 16; s++) acc += base[(size_t)s * QW];
    } else {
        const float* io = g_io + (isk ? (size_t)NT * 8 : 0) + ((size_t)(b * SS + s0)) * 8 + h;
        for (int s = 0; s < SS / 16; s++) acc += base[(size_t)s * QW] / io[(size_t)s * 8];
    }
    g_part[(chunk * 32 + bh) * 128 + tid] = acc;
}

__global__ __launch_bounds__(256) void reduce_stage2(int phase)
{
    int idx = blockIdx.x * 256 + threadIdx.x;
    float acc = 0.f;
#pragma unroll
    for (int c = 0; c < 16; c++) acc += g_part[c * 4096 + idx];
    int bh = idx >> 7, t = idx & 127;
    int isk = t >> 6, d = t & 63;
    g_sums[(size_t)(phase * 2 + isk) * 2048 + bh * 64 + d] = acc;
}

// ---------------- per-token dots: warp per token ------------------------------
__global__ __launch_bounds__(256) void dots_kernel(int phase)
{
    int warp = threadIdx.x >> 5, lane = threadIdx.x & 31;
    int tok  = blockIdx.x * 8 + warp;
    int b    = tok >> 12;

    __shared__ float sQ[8][64], sK[8][64];
    const float* vq = g_sums + (size_t)(phase == 0 ? 1 : 3) * 2048 + b * 512;
    const float* vk = g_sums + (size_t)(phase == 0 ? 0 : 2) * 2048 + b * 512;
    for (int idx = threadIdx.x; idx < 512; idx += 256) {
        sQ[idx >> 6][idx & 63] = vq[idx];
        sK[idx >> 6][idx & 63] = vk[idx];
    }
    __syncthreads();

    const float* tq = g_qkv + (size_t)tok * QW;
    float* outI = (phase == 0 ? g_io : g_hat) + (size_t)tok * 8;
    float* outO = outI + (size_t)NT * 8;

#pragma unroll
    for (int h = 0; h < 8; h++) {
        const float* qh = tq + h * 192;
        float vi = qh[lane] * sQ[h][lane] + qh[lane + 32] * sQ[h][lane + 32];
        float vo = qh[64 + lane] * sK[h][lane] + qh[64 + lane + 32] * sK[h][lane + 32];
#pragma unroll
        for (int off = 16; off; off >>= 1) {
            vi += __shfl_down_sync(0xFFFFFFFFu, vi, off);
            vo += __shfl_down_sync(0xFFFFFFFFu, vo, off);
        }
        if (lane == 0) { outI[h] = vi; outO[h] = vo; }
    }
}

// ---------------- softmax stats over seq per (b,h) ---------------------------
__global__ __launch_bounds__(256) void softmax_stats()
{
    int bh = blockIdx.x;
    int b = bh >> 3, h = bh & 7;
    __shared__ float red[256];
    const float* oh = g_hat + (size_t)NT * 8 + (size_t)b * SS * 8 + h;

    float m = -1e30f;
    for (int s = threadIdx.x; s < SS; s += 256) m = fmaxf(m, oh[(size_t)s * 8]);
    red[threadIdx.x] = m; __syncthreads();
    for (int o = 128; o; o >>= 1) {
        if (threadIdx.x < o) red[threadIdx.x] = fmaxf(red[threadIdx.x], red[threadIdx.x + o]);
        __syncthreads();
    }
    m = red[0]; __syncthreads();

    float sum = 0.f;
    for (int s = threadIdx.x; s < SS; s += 256) sum += expf(oh[(size_t)s * 8] - m);
    red[threadIdx.x] = sum; __syncthreads();
    for (int o = 128; o; o >>= 1) {
        if (threadIdx.x < o) red[threadIdx.x] += red[threadIdx.x + o];
        __syncthreads();
    }
    if (threadIdx.x == 0) { g_sm[bh] = m; g_sm[32 + bh] = red[0]; }
}

// -------- fused flow-attention core (emits scaled fp16 hi/lo values) ---------
__global__ __launch_bounds__(256) void token_kernel()
{
    int lt = threadIdx.x >> 6;
    int e  = threadIdx.x & 63;
    int tok = blockIdx.x * 4 + lt;
    int b   = tok >> 12;

    __shared__ float qi[4][8][65], kk[4][8][65], vw[4][8][65];
    __shared__ float Am[4][8][9];
    __shared__ float s_invi[4][8], s_sig[4][8], s_sm[4][8];

    const float* tq = g_qkv + (size_t)tok * QW;
    if (e < 8) {
        int h = e;
        float iv = g_io[(size_t)tok * 8 + h];
        float ih = g_hat[(size_t)tok * 8 + h];
        float oh = g_hat[(size_t)NT * 8 + (size_t)tok * 8 + h];
        int bh = b * 8 + h;
        s_invi[lt][h] = 1.0f / iv;
        s_sig[lt][h]  = 1.0f / (1.0f + expf(-ih));
        s_sm[lt][h]   = expf(oh - g_sm[bh]) / g_sm[32 + bh];
    }
    __syncthreads();

#pragma unroll
    for (int h = 0; h < 8; h++) {
        qi[lt][h][e] = tq[h * 192 + e] * s_invi[lt][h];
        kk[lt][h][e] = tq[h * 192 + 64 + e];
        vw[lt][h][e] = tq[h * 192 + 128 + e] * s_sm[lt][h];
    }
    __syncthreads();

    {
        int h = e >> 3, h2 = e & 7;
        float a = 0.f;
#pragma unroll 8
        for (int d = 0; d < 64; d++) a = fmaf(qi[lt][h][d], kk[lt][h2][d], a);
        Am[lt][h][h2] = a;
    }
    __syncthreads();

    __half* ovh = g_vhi + (size_t)tok * EE;
    __half* ovl = g_vlo + (size_t)tok * EE;
#pragma unroll
    for (int h = 0; h < 8; h++) {
        float acc = 0.f;
#pragma unroll
        for (int h2 = 0; h2 < 8; h2++) acc = fmaf(Am[lt][h][h2], vw[lt][h2][e], acc);
        // scale by 2^20 so fp16 hi/lo stay in the normal range (values ~1e-7)
        float vs = acc * s_sig[lt][h] * VAL_SCALE;
        __half hv = __float2half(vs);
        ovh[h * 64 + e] = hv;
        ovl[h * 64 + e] = __float2half(vs - __half2float(hv));
    }
}

// ---------------- launch ------------------------------------------------------
extern "C" void kernel_launch(void* const* d_in, const int* in_sizes, int n_in,
                              void* d_out, int out_size)
{
    (void)in_sizes; (void)n_in; (void)out_size;
    const float* x     = (const float*)d_in[0];
    const float* W_qkv = (const float*)d_in[1];
    const float* b_qkv = (const float*)d_in[2];
    const float* W_out = (const float*)d_in[3];
    const float* b_out = (const float*)d_in[4];
    float* out = (float*)d_out;

    float* p_qkv = nullptr;
    cudaGetSymbolAddress((void**)&p_qkv, g_qkv);
    __half *p_xhi, *p_xlo, *p_whi, *p_wohi, *p_vhi, *p_vlo;
    cudaGetSymbolAddress((void**)&p_xhi,  g_xhi);
    cudaGetSymbolAddress((void**)&p_xlo,  g_xlo);
    cudaGetSymbolAddress((void**)&p_whi,  g_whi);
    cudaGetSymbolAddress((void**)&p_wohi, g_wohi);
    cudaGetSymbolAddress((void**)&p_vhi,  g_vhi);
    cudaGetSymbolAddress((void**)&p_vlo,  g_vlo);

    cudaFuncSetAttribute(hmma_gemm, cudaFuncAttributeMaxDynamicSharedMemorySize,
                         SMEM_GEMM);

    // 0) convert operands to fp16 hi/lo
    {
        int n4 = NT * EE / 4;
        cvt_split<<<(n4 + 255) / 256, 256>>>((const float4*)x,
                                             (__half2*)p_xhi, (__half2*)p_xlo, n4);
        int w4 = QW * EE / 4;
        cvt_hi<<<(w4 + 255) / 256, 256>>>((const float4*)W_qkv, (__half2*)p_whi, w4);
        int o4 = EE * EE / 4;
        cvt_hi<<<(o4 + 255) / 256, 256>>>((const float4*)W_out, (__half2*)p_wohi, o4);
    }
    // 1) QKV projection (HMMA split-fp16) + sigmoid(q,k) epilogue
    hmma_gemm<<<dim3(QW / 128, NT / 256), 512, SMEM_GEMM>>>(
        p_xhi, p_xlo, p_whi, b_qkv, p_qkv, QW, EE, 1, 1.0f);
    // 2) sumQ/sumK over seq
    reduce_stage1<<<dim3(16, 32), 128>>>(0);
    reduce_stage2<<<16, 256>>>(0);
    // 3) i, o per (token, head)
    dots_kernel<<<NT / 8, 256>>>(0);
    // 4) sqd = sum q/i, skd = sum k/o
    reduce_stage1<<<dim3(16, 32), 128>>>(1);
    reduce_stage2<<<16, 256>>>(1);
    // 5) ihat, ohat
    dots_kernel<<<NT / 8, 256>>>(1);
    // 6) softmax stats
    softmax_stats<<<32, 256>>>();
    // 7) fused flow-attention core -> scaled values (fp16 hi/lo)
    token_kernel<<<NT / 4, 256>>>();
    // 8) output projection (HMMA split-fp16), unscale in epilogue
    hmma_gemm<<<dim3(EE / 128, NT / 256), 512, SMEM_GEMM>>>(
        p_vhi, p_vlo, p_wohi, b_out, out, EE, EE, 0, VAL_INV_SCALE);
}